// round 1
// baseline (speedup 1.0000x reference)
#include <cuda_runtime.h>

// Problem constants
#define H   8
#define Bn  32768
#define INF 16
#define CI  32
#define OF  32
#define Kk  544                   // OF*(INF+1)
#define WSZ (CI*(INF+1)*OF)       // 17408 floats per head, layout [c][i][o]

// Scratch for pre-transposed weights (device globals: the sanctioned no-alloc scratch)
__device__ float g_wt[H * WSZ];   // [h][(c*17+i)*32 + o]
__device__ float g_bt[H * Kk];    // [h][i*32 + o]

// ---- packed f32x2 helpers (Blackwell FFMA2 path) ----
static __device__ __forceinline__ unsigned long long pack2(float lo, float hi) {
    unsigned long long r;
    asm("mov.b64 %0, {%1, %2};" : "=l"(r) : "f"(lo), "f"(hi));
    return r;
}
static __device__ __forceinline__ void unpack2(unsigned long long v, float& lo, float& hi) {
    asm("mov.b64 {%0, %1}, %2;" : "=f"(lo), "=f"(hi) : "l"(v));
}
static __device__ __forceinline__ unsigned long long fma2(unsigned long long a,
                                                          unsigned long long b,
                                                          unsigned long long c) {
    unsigned long long d;
    asm("fma.rn.f32x2 %0, %1, %2, %3;" : "=l"(d) : "l"(a), "l"(b), "l"(c));
    return d;
}

// Pre-kernel: transpose cond_weight (h, k=o*17+i, c) -> g_wt [h][(c*17+i)*32+o]
// and cond_bias (h, k) -> g_bt [h][i*32+o]. Coalesced reads, scattered writes (tiny).
__global__ void mml_transpose_k(const float* __restrict__ cw, const float* __restrict__ cb) {
    int idx = blockIdx.x * blockDim.x + threadIdx.x;
    if (idx < H * Kk * CI) {
        int c = idx % CI;
        int k = (idx / CI) % Kk;
        int h = idx / (CI * Kk);
        int o = k / 17, i = k % 17;
        g_wt[h * WSZ + (c * 17 + i) * OF + o] = cw[idx];
    }
    if (idx < H * Kk) {
        int k = idx % Kk;
        int h = idx / Kk;
        int o = k / 17, i = k % 17;
        g_bt[h * Kk + i * OF + o] = cb[idx];
    }
}

// Main kernel: blockIdx.y = head, blockIdx.x = 256-sample tile. 1 thread = 1 sample.
// out[o] = sum_c cond[c] * (sum_{i<16} W[o,i,c]*x[i] + W[o,16,c])
//        + sum_{i<16} bias[o,i]*x[i] + bias[o,16]
__global__ void __launch_bounds__(256, 1)
mml_main_k(const float* __restrict__ input, const float* __restrict__ cond,
           float* __restrict__ out) {
    extern __shared__ float sh[];
    float* sW = sh;          // WSZ floats: [c][i][o]
    float* sB = sh + WSZ;    // Kk floats:  [i][o]

    const int h = blockIdx.y;

    // Cooperative, coalesced, conflict-free smem fill from pre-transposed globals.
    {
        const float4* g4 = reinterpret_cast<const float4*>(g_wt + h * WSZ);
        float4* s4 = reinterpret_cast<float4*>(sW);
        for (int t = threadIdx.x; t < WSZ / 4; t += 256) s4[t] = g4[t];
        const float4* gb = reinterpret_cast<const float4*>(g_bt + h * Kk);
        float4* sb = reinterpret_cast<float4*>(sB);
        for (int t = threadIdx.x; t < Kk / 4; t += 256) sb[t] = gb[t];
    }
    __syncthreads();

    const int b = blockIdx.x * 256 + threadIdx.x;
    const float* xin = input + (h * Bn + b) * INF;
    const float* cin = cond + (h * Bn + b) * CI;
    float* op = out + (h * Bn + b) * OF;

    // x[i] duplicated into both f32x2 halves (register-resident, reused 32*8 times)
    unsigned long long xb[16];
#pragma unroll
    for (int i = 0; i < 16; i += 4) {
        float4 v = *reinterpret_cast<const float4*>(xin + i);
        xb[i + 0] = pack2(v.x, v.x);
        xb[i + 1] = pack2(v.y, v.y);
        xb[i + 2] = pack2(v.z, v.z);
        xb[i + 3] = pack2(v.w, v.w);
    }

    // q-loop: 4 outputs (2 f32x2 accumulators) per iteration. Kept rolled for I$.
#pragma unroll 1
    for (int q = 0; q < 8; q++) {
        const float* wq = sW + q * 4;

        // init accumulators with the bias term: o = bias[o,16] + sum_i bias[o,i]*x[i]
        ulonglong2 bv = *reinterpret_cast<const ulonglong2*>(sB + 16 * OF + q * 4);
        unsigned long long o0 = bv.x, o1 = bv.y;
#pragma unroll
        for (int i = 0; i < 16; i++) {
            ulonglong2 w = *reinterpret_cast<const ulonglong2*>(sB + i * OF + q * 4);
            o0 = fma2(w.x, xb[i], o0);
            o1 = fma2(w.y, xb[i], o1);
        }

        // c-loop, 4-way unrolled body inside a rolled loop (cond via L1-hit LDG.128)
#pragma unroll 1
        for (int c4 = 0; c4 < CI; c4 += 4) {
            float4 cv = *reinterpret_cast<const float4*>(cin + c4);
#pragma unroll
            for (int u = 0; u < 4; u++) {
                const int c = c4 + u;
                const float* wc = wq + c * (17 * OF);
                // A init = W[o, i=16, c] (homogeneous x1[16] = 1)
                ulonglong2 ai = *reinterpret_cast<const ulonglong2*>(wc + 16 * OF);
                unsigned long long a0 = ai.x, a1 = ai.y;
#pragma unroll
                for (int i = 0; i < 16; i++) {
                    ulonglong2 w = *reinterpret_cast<const ulonglong2*>(wc + i * OF);
                    a0 = fma2(w.x, xb[i], a0);
                    a1 = fma2(w.y, xb[i], a1);
                }
                float cs = (u == 0) ? cv.x : (u == 1) ? cv.y : (u == 2) ? cv.z : cv.w;
                unsigned long long cb2 = pack2(cs, cs);
                o0 = fma2(a0, cb2, o0);
                o1 = fma2(a1, cb2, o1);
            }
        }

        float r0, r1, r2, r3;
        unpack2(o0, r0, r1);
        unpack2(o1, r2, r3);
        *reinterpret_cast<float4*>(op + q * 4) = make_float4(r0, r1, r2, r3);
    }
}

extern "C" void kernel_launch(void* const* d_in, const int* in_sizes, int n_in,
                              void* d_out, int out_size) {
    const float* input = (const float*)d_in[0];   // (8, 32768, 16)
    const float* cond  = (const float*)d_in[1];   // (8, 32768, 32)
    const float* cw    = (const float*)d_in[2];   // (8, 544, 32)
    const float* cb    = (const float*)d_in[3];   // (8, 544)
    float* out = (float*)d_out;                   // (8, 32768, 32)

    // Stage 1: transpose weights into compute-friendly layout
    int total = H * Kk * CI;
    mml_transpose_k<<<(total + 255) / 256, 256>>>(cw, cb);

    // Stage 2: main compute (needs >48KB dynamic smem)
    const int smem_bytes = (WSZ + Kk) * (int)sizeof(float);  // 71808 + 2176
    cudaFuncSetAttribute(mml_main_k, cudaFuncAttributeMaxDynamicSharedMemorySize, smem_bytes);
    dim3 grid(Bn / 256, H);
    mml_main_k<<<grid, 256, smem_bytes>>>(input, cond, out);
}

// round 2
// speedup vs baseline: 1.3896x; 1.3896x over previous
#include <cuda_runtime.h>

// Problem constants
#define H    8
#define Bn   32768
#define INF  16
#define CI   32
#define OF   32
#define Kk   544                    // OF*(INF+1)
#define NCH  33                     // 32 cond channels + 1 bias channel (cond==1)
#define WSZ  (NCH*(INF+1)*OF)       // 17952 floats per head, layout [ch][i][o]

// Scratch for pre-transposed weights (device globals: sanctioned no-alloc scratch)
__device__ float g_wt[H * WSZ];     // [h][(ch*17+i)*32 + o]; ch==32 is the bias row

// ---- packed f32x2 helpers (Blackwell FFMA2 path) ----
static __device__ __forceinline__ unsigned long long pack2(float lo, float hi) {
    unsigned long long r;
    asm("mov.b64 %0, {%1, %2};" : "=l"(r) : "f"(lo), "f"(hi));
    return r;
}
static __device__ __forceinline__ void unpack2(unsigned long long v, float& lo, float& hi) {
    asm("mov.b64 {%0, %1}, %2;" : "=f"(lo), "=f"(hi) : "l"(v));
}
static __device__ __forceinline__ unsigned long long fma2(unsigned long long a,
                                                          unsigned long long b,
                                                          unsigned long long c) {
    unsigned long long d;
    asm("fma.rn.f32x2 %0, %1, %2, %3;" : "=l"(d) : "l"(a), "l"(b), "l"(c));
    return d;
}

// Pre-kernel: transpose cond_weight (h, k=o*17+i, c) -> g_wt [h][(c*17+i)*32+o],
// and cond_bias (h, k=o*17+i) -> channel 32. Tiny (~590K elements).
__global__ void mml_transpose_k(const float* __restrict__ cw, const float* __restrict__ cb) {
    int idx = blockIdx.x * blockDim.x + threadIdx.x;
    if (idx < H * Kk * CI) {
        int c = idx % CI;
        int k = (idx / CI) % Kk;
        int h = idx / (CI * Kk);
        int o = k / 17, i = k % 17;
        g_wt[h * WSZ + (c * 17 + i) * OF + o] = cw[idx];
    }
    if (idx < H * Kk) {
        int k = idx % Kk;
        int h = idx / Kk;
        int o = k / 17, i = k % 17;
        g_wt[h * WSZ + (32 * 17 + i) * OF + o] = cb[idx];
    }
}

// Main kernel: blockIdx.y = head, blockIdx.x = 512-sample tile.
// Each thread computes TWO samples (b, b+256), sharing every weight load.
// out[o] = sum_{ch<33} cond1[ch] * ( sum_{i<16} W[ch,i,o]*x[i] + W[ch,16,o] )
// where cond1[32] = 1 (bias channel).
__global__ void __launch_bounds__(256, 1)
mml_main_k(const float* __restrict__ input, const float* __restrict__ cond,
           float* __restrict__ out) {
    extern __shared__ float sh[];
    float* sW = sh;   // WSZ floats: [ch][i][o]

    const int h = blockIdx.y;

    // Cooperative, coalesced smem fill (17952 floats = 4488 float4)
    {
        const float4* g4 = reinterpret_cast<const float4*>(g_wt + h * WSZ);
        float4* s4 = reinterpret_cast<float4*>(sW);
#pragma unroll 1
        for (int t = threadIdx.x; t < WSZ / 4; t += 256) s4[t] = g4[t];
    }
    __syncthreads();

    const int b0 = blockIdx.x * 512 + threadIdx.x;
    const int b1 = b0 + 256;
    const float* x0p = input + (h * Bn + b0) * INF;
    const float* x1p = input + (h * Bn + b1) * INF;
    const float* c0p = cond + (h * Bn + b0) * CI;
    const float* c1p = cond + (h * Bn + b1) * CI;
    float* o0p = out + (h * Bn + b0) * OF;
    float* o1p = out + (h * Bn + b1) * OF;

    // x[i] duplicated into both f32x2 halves, for both samples (64 regs)
    unsigned long long xa[16], xb[16];
#pragma unroll
    for (int i = 0; i < 16; i += 4) {
        float4 v0 = *reinterpret_cast<const float4*>(x0p + i);
        float4 v1 = *reinterpret_cast<const float4*>(x1p + i);
        xa[i + 0] = pack2(v0.x, v0.x); xb[i + 0] = pack2(v1.x, v1.x);
        xa[i + 1] = pack2(v0.y, v0.y); xb[i + 1] = pack2(v1.y, v1.y);
        xa[i + 2] = pack2(v0.z, v0.z); xb[i + 2] = pack2(v1.z, v1.z);
        xa[i + 3] = pack2(v0.w, v0.w); xb[i + 3] = pack2(v1.w, v1.w);
    }

    // q-loop: 4 outputs (2 f32x2 accumulators per sample). Rolled for I$.
#pragma unroll 1
    for (int q = 0; q < 8; q++) {
        const float* wq = sW + q * 4;

        unsigned long long s00 = 0, s01 = 0;  // sample0, outputs q*4..q*4+3
        unsigned long long s10 = 0, s11 = 0;  // sample1

        // channels 0..31 (cond), 4-way unrolled body in a rolled loop
#pragma unroll 1
        for (int c4 = 0; c4 < CI; c4 += 4) {
            float4 cv0 = *reinterpret_cast<const float4*>(c0p + c4);
            float4 cv1 = *reinterpret_cast<const float4*>(c1p + c4);
#pragma unroll
            for (int u = 0; u < 4; u++) {
                const float* wc = wq + (c4 + u) * (17 * OF);
                // a = W[ch, i=16, o-pair] (homogeneous term), then += W[ch,i,o]*x[i]
                ulonglong2 wi = *reinterpret_cast<const ulonglong2*>(wc + 16 * OF);
                unsigned long long a00 = wi.x, a01 = wi.y;   // sample0
                unsigned long long a10 = wi.x, a11 = wi.y;   // sample1
#pragma unroll
                for (int i = 0; i < 16; i++) {
                    ulonglong2 w = *reinterpret_cast<const ulonglong2*>(wc + i * OF);
                    a00 = fma2(w.x, xa[i], a00);
                    a01 = fma2(w.y, xa[i], a01);
                    a10 = fma2(w.x, xb[i], a10);
                    a11 = fma2(w.y, xb[i], a11);
                }
                float cs0 = (u == 0) ? cv0.x : (u == 1) ? cv0.y : (u == 2) ? cv0.z : cv0.w;
                float cs1 = (u == 0) ? cv1.x : (u == 1) ? cv1.y : (u == 2) ? cv1.z : cv1.w;
                unsigned long long cp0 = pack2(cs0, cs0);
                unsigned long long cp1 = pack2(cs1, cs1);
                s00 = fma2(a00, cp0, s00);
                s01 = fma2(a01, cp0, s01);
                s10 = fma2(a10, cp1, s10);
                s11 = fma2(a11, cp1, s11);
            }
        }

        // bias channel (ch = 32, cond = 1): accumulate directly
        {
            const float* wc = wq + 32 * (17 * OF);
            ulonglong2 wi = *reinterpret_cast<const ulonglong2*>(wc + 16 * OF);
            unsigned long long a00 = wi.x, a01 = wi.y;
            unsigned long long a10 = wi.x, a11 = wi.y;
#pragma unroll
            for (int i = 0; i < 16; i++) {
                ulonglong2 w = *reinterpret_cast<const ulonglong2*>(wc + i * OF);
                a00 = fma2(w.x, xa[i], a00);
                a01 = fma2(w.y, xa[i], a01);
                a10 = fma2(w.x, xb[i], a10);
                a11 = fma2(w.y, xb[i], a11);
            }
            unsigned long long one = pack2(1.0f, 1.0f);
            s00 = fma2(a00, one, s00);
            s01 = fma2(a01, one, s01);
            s10 = fma2(a10, one, s10);
            s11 = fma2(a11, one, s11);
        }

        float r0, r1, r2, r3;
        unpack2(s00, r0, r1); unpack2(s01, r2, r3);
        *reinterpret_cast<float4*>(o0p + q * 4) = make_float4(r0, r1, r2, r3);
        unpack2(s10, r0, r1); unpack2(s11, r2, r3);
        *reinterpret_cast<float4*>(o1p + q * 4) = make_float4(r0, r1, r2, r3);
    }
}

extern "C" void kernel_launch(void* const* d_in, const int* in_sizes, int n_in,
                              void* d_out, int out_size) {
    const float* input = (const float*)d_in[0];   // (8, 32768, 16)
    const float* cond  = (const float*)d_in[1];   // (8, 32768, 32)
    const float* cw    = (const float*)d_in[2];   // (8, 544, 32)
    const float* cb    = (const float*)d_in[3];   // (8, 544)
    float* out = (float*)d_out;                   // (8, 32768, 32)

    // Stage 1: transpose weights (+bias as channel 32) into compute layout
    int total = H * Kk * CI;
    mml_transpose_k<<<(total + 255) / 256, 256>>>(cw, cb);

    // Stage 2: main compute
    const int smem_bytes = WSZ * (int)sizeof(float);  // 71808
    cudaFuncSetAttribute(mml_main_k, cudaFuncAttributeMaxDynamicSharedMemorySize, smem_bytes);
    dim3 grid(Bn / 512, H);
    mml_main_k<<<grid, 256, smem_bytes>>>(input, cond, out);
}